// round 3
// baseline (speedup 1.0000x reference)
#include <cuda_runtime.h>

// ---------------------------------------------------------------------------
// pitch_predictor: 4-layer biLSTM (B=128,T=2048,H=16) -> x[:,7::8,:] ->
//                  4-layer uniLSTM (H=1) -> out (128,256,1) fp32
// Latency-bound recurrence. One warp per (batch,direction); weights in regs;
// input projection fused; redundant dual-lane cell state kills one shuffle.
// ---------------------------------------------------------------------------

#define FULL 0xffffffffu
static const int T_ = 2048;

// ping-pong inter-layer buffers (128*2048*32 floats = 33.5 MB each, L2-resident)
__device__ float g_bufA[128 * 2048 * 32];
__device__ float g_bufB[128 * 2048 * 32];
__device__ float g_unixw[128 * 256 * 4];
__device__ float g_unih[256 * 128];

__device__ __forceinline__ float fast_ex2(float x) {
    float y; asm("ex2.approx.f32 %0, %1;" : "=f"(y) : "f"(x)); return y;
}
__device__ __forceinline__ float fast_rcp(float x) {
    float y; asm("rcp.approx.f32 %0, %1;" : "=f"(y) : "f"(x)); return y;
}
// sigmoid(x) = 1 / (1 + 2^(-x*log2(e)))   (~few-ulp accurate)
__device__ __forceinline__ float sigm(float x) {
    float e = fast_ex2(-1.4426950408889634f * x);
    return fast_rcp(1.0f + e);
}
// tanh(x) = 2*sigmoid(2x) - 1
__device__ __forceinline__ float tanh_(float x) {
    float e = fast_ex2(-2.8853900817779268f * x);
    float r = fast_rcp(1.0f + e);
    return fmaf(2.0f, r, -1.0f);
}

// ---------------------------------------------------------------------------
// Bidirectional LSTM layer.
// grid = 64 blocks x 128 threads. Blocks 0..31: forward dir, 32..63: backward.
// Each block: 4 warps = 4 batches. Lane u owns gates u (i|f) and u+32 (g|o).
// Lanes u and u+16 both maintain c[u&15], h[u&15] (identical copies).
// SRC/DST: 0 = external pointer, 1 = g_bufA, 2 = g_bufB.
// ---------------------------------------------------------------------------
template <int IN, int SRC, int DST>
__global__ void __launch_bounds__(128, 1)
bilstm_kernel(const float* __restrict__ xin_param,
              const float* __restrict__ Wih_base,   // [2][64][IN] (dir-major)
              const float* __restrict__ Whh_base,   // [2][64][16]
              const float* __restrict__ b_base)     // [2][64]
{
    const float* __restrict__ xin =
        (SRC == 0) ? xin_param : (SRC == 1 ? g_bufA : g_bufB);
    float* __restrict__ outp = (DST == 1) ? g_bufA : g_bufB;

    const int warp  = threadIdx.x >> 5;
    const int lane  = threadIdx.x & 31;
    const int dir   = blockIdx.x >> 5;                 // 0 fwd, 1 bwd
    const int batch = ((blockIdx.x & 31) << 2) + warp; // 0..127

    const int g0 = lane;        // gate in [i|f] block
    const int g1 = lane + 32;   // gate in [g|o] block

    const float* __restrict__ Wih  = Wih_base + dir * 64 * IN;
    const float* __restrict__ Whh  = Whh_base + dir * 64 * 16;
    const float* __restrict__ bias = b_base   + dir * 64;

    float wih0[IN], wih1[IN];
    float whh0[16], whh1[16];
#pragma unroll
    for (int k = 0; k < IN; k++) { wih0[k] = Wih[g0 * IN + k]; wih1[k] = Wih[g1 * IN + k]; }
#pragma unroll
    for (int j = 0; j < 16; j++) { whh0[j] = Whh[g0 * 16 + j]; whh1[j] = Whh[g1 * 16 + j]; }
    const float b0 = bias[g0];
    const float b1 = bias[g1];

    const int base_in  = batch * T_ * IN;
    const int base_out = batch * T_ * 32 + dir * 16;

    const int dt = dir ? -1 : 1;
    int t = dir ? (T_ - 1) : 0;

    float hval = 0.0f, c = 0.0f;
    const bool hi = (lane >= 16);

    // distance-2 x prefetch
    float xv0 = (lane < IN) ? __ldg(&xin[base_in + t * IN + lane]) : 0.0f;
    float xv1 = (lane < IN) ? __ldg(&xin[base_in + (t + dt) * IN + lane]) : 0.0f;

    for (int s = 0; s < T_; ++s) {
        float xv = xv0;
        xv0 = xv1;
        if (s + 2 < T_) {
            xv1 = (lane < IN) ? __ldg(&xin[base_in + (t + 2 * dt) * IN + lane]) : 0.0f;
        }

        // ---- input projection (off the recurrence chain) ----
        float xw0 = b0, xw1 = b1;
#pragma unroll
        for (int k = 0; k < IN; k++) {
            float xk = __shfl_sync(FULL, xv, k);
            xw0 = fmaf(xk, wih0[k], xw0);
            xw1 = fmaf(xk, wih1[k], xw1);
        }

        // ---- recurrent dot: h(16) . Whh[g] (4-way split chains) ----
        float a0 = 0.f, a1 = 0.f, a2 = 0.f, a3 = 0.f;
#pragma unroll
        for (int j = 0; j < 16; j += 2) {
            float hj0 = __shfl_sync(FULL, hval, j);
            float hj1 = __shfl_sync(FULL, hval, j + 1);
            a0 = fmaf(hj0, whh0[j],     a0);
            a1 = fmaf(hj1, whh0[j + 1], a1);
            a2 = fmaf(hj0, whh1[j],     a2);
            a3 = fmaf(hj1, whh1[j + 1], a3);
        }
        float pre0 = xw0 + (a0 + a1);   // i (lo) | f (hi)
        float pre1 = xw1 + (a2 + a3);   // g (lo) | o (hi)

        // ---- activations ----
        float s0 = sigm(pre0);                       // sig(i) | sig(f)
        float m1 = hi ? pre1 : (pre1 + pre1);
        float rr = sigm(m1);
        float v1 = hi ? rr : fmaf(2.0f, rr, -1.0f);  // sig(o) | tanh(g)

        float myA = hi ? s0 : (s0 * v1);  // sig(f) | sig(i)*tanh(g)
        float myB = v1;                   // sig(o) | (unused by peer)

        float oA = __shfl_xor_sync(FULL, myA, 16);
        float oB = __shfl_xor_sync(FULL, myB, 16);

        float prod = hi ? oA  : myA;
        float sf   = hi ? myA : oA;
        float so   = hi ? myB : oB;

        c = fmaf(sf, c, prod);
        float tc = tanh_(c);
        hval = so * tc;                   // h[lane & 15] on both halves

        if (!hi) outp[base_out + t * 32 + lane] = hval;
        t += dt;
    }
}

// ---------------------------------------------------------------------------
// Precompute input projection for uni-LSTM layer 0 from downsampled biLSTM out.
// One thread per (b, t'); t' in [0,256), source t = 8*t'+7.
// ---------------------------------------------------------------------------
__global__ void uni_xw_kernel(const float* __restrict__ uWih0,  // [4][32]
                              const float* __restrict__ ub)     // [4][4]
{
    int idx = blockIdx.x * blockDim.x + threadIdx.x;  // 0..32767
    if (idx >= 128 * 256) return;
    int b  = idx >> 8;
    int tt = idx & 255;
    const float* __restrict__ xr = g_bufB + (b * T_ + (tt * 8 + 7)) * 32;
    float x[32];
#pragma unroll
    for (int k = 0; k < 32; k++) x[k] = xr[k];
#pragma unroll
    for (int g = 0; g < 4; g++) {
        float acc = __ldg(&ub[g]);  // layer 0 bias
#pragma unroll
        for (int k = 0; k < 32; k++) acc = fmaf(x[k], __ldg(&uWih0[g * 32 + k]), acc);
        g_unixw[idx * 4 + g] = acc;
    }
}

// ---------------------------------------------------------------------------
// 4-layer unidirectional LSTM, H=1. One thread per batch (fully independent).
// ---------------------------------------------------------------------------
__global__ void uni_rec_kernel(const float* __restrict__ uWih,  // [3][4][1]
                               const float* __restrict__ uWhh,  // [4][4][1]
                               const float* __restrict__ ub,    // [4][4]
                               float* __restrict__ outp)        // [128][256]
{
    int b = blockIdx.x * blockDim.x + threadIdx.x;
    if (b >= 128) return;

    // layer 0: xw precomputed
    {
        float h = 0.f, c = 0.f;
        const float w0 = uWhh[0], w1 = uWhh[1], w2 = uWhh[2], w3 = uWhh[3];
        for (int t = 0; t < 256; t++) {
            const float* xw = &g_unixw[(b * 256 + t) * 4];
            float gi = fmaf(h, w0, xw[0]);
            float gf = fmaf(h, w1, xw[1]);
            float gg = fmaf(h, w2, xw[2]);
            float go = fmaf(h, w3, xw[3]);
            c = fmaf(sigm(gf), c, sigm(gi) * tanh_(gg));
            h = sigm(go) * tanh_(c);
            g_unih[t * 128 + b] = h;
        }
    }
    // layers 1..3: scalar input = previous layer h
    for (int l = 1; l < 4; l++) {
        const float* wih = uWih + (l - 1) * 4;
        const float* whh = uWhh + l * 4;
        const float* bb  = ub + l * 4;
        const float vi0 = wih[0], vi1 = wih[1], vi2 = wih[2], vi3 = wih[3];
        const float w0 = whh[0], w1 = whh[1], w2 = whh[2], w3 = whh[3];
        const float c0 = bb[0], c1 = bb[1], c2 = bb[2], c3 = bb[3];
        float h = 0.f, c = 0.f;
        for (int t = 0; t < 256; t++) {
            float xx = g_unih[t * 128 + b];
            float gi = fmaf(h, w0, fmaf(xx, vi0, c0));
            float gf = fmaf(h, w1, fmaf(xx, vi1, c1));
            float gg = fmaf(h, w2, fmaf(xx, vi2, c2));
            float go = fmaf(h, w3, fmaf(xx, vi3, c3));
            c = fmaf(sigm(gf), c, sigm(gi) * tanh_(gg));
            h = sigm(go) * tanh_(c);
            if (l == 3) outp[b * 256 + t] = h;
            else        g_unih[t * 128 + b] = h;
        }
    }
}

// ---------------------------------------------------------------------------
extern "C" void kernel_launch(void* const* d_in, const int* in_sizes, int n_in,
                              void* d_out, int out_size)
{
    const float* x     = (const float*)d_in[0];  // (128,2048,24)
    const float* bWih0 = (const float*)d_in[1];  // (2,64,24)
    const float* bWih  = (const float*)d_in[2];  // (3,2,64,32)
    const float* bWhh  = (const float*)d_in[3];  // (4,2,64,16)
    const float* bb    = (const float*)d_in[4];  // (4,2,64)
    const float* uWih0 = (const float*)d_in[5];  // (4,32)
    const float* uWih  = (const float*)d_in[6];  // (3,4,1)
    const float* uWhh  = (const float*)d_in[7];  // (4,4,1)
    const float* ub    = (const float*)d_in[8];  // (4,4)
    float* out = (float*)d_out;                  // (128,256,1)

    dim3 grid(64), block(128);

    // layer 0: external input (IN=24) -> bufA
    bilstm_kernel<24, 0, 1><<<grid, block>>>(x, bWih0,
                                             bWhh + 0 * 2 * 64 * 16,
                                             bb   + 0 * 2 * 64);
    // layer 1: bufA -> bufB
    bilstm_kernel<32, 1, 2><<<grid, block>>>(nullptr, bWih + 0 * 2 * 64 * 32,
                                             bWhh + 1 * 2 * 64 * 16,
                                             bb   + 1 * 2 * 64);
    // layer 2: bufB -> bufA
    bilstm_kernel<32, 2, 1><<<grid, block>>>(nullptr, bWih + 1 * 2 * 64 * 32,
                                             bWhh + 2 * 2 * 64 * 16,
                                             bb   + 2 * 2 * 64);
    // layer 3: bufA -> bufB
    bilstm_kernel<32, 1, 2><<<grid, block>>>(nullptr, bWih + 2 * 2 * 64 * 32,
                                             bWhh + 3 * 2 * 64 * 16,
                                             bb   + 3 * 2 * 64);

    // uni-LSTM stack
    uni_xw_kernel<<<128, 256>>>(uWih0, ub);
    uni_rec_kernel<<<4, 32>>>(uWih, uWhh, ub, out);
}

// round 7
// speedup vs baseline: 1.2823x; 1.2823x over previous
#include <cuda_runtime.h>

#define FULL 0xffffffffu
typedef unsigned long long u64;

// ---------------------------------------------------------------------------
// pitch_predictor: 4-layer biLSTM (B=128,T=2048,H=16) -> x[:,7::8,:] ->
//                  4-layer uniLSTM (H=1) -> out (128,256,1) fp32
// Phase split: parallel xW GEMM per layer (throughput kernel) + 16-lane
// recurrence warps (latency kernel, 2 recurrences per warp, no gate exchange).
// ---------------------------------------------------------------------------

__device__ float g_xw[128 * 2 * 2048 * 64];  // gate preacts (bias folded), reused per layer
__device__ float g_hA[128 * 2048 * 32];      // inter-layer h ping
__device__ float g_hB[128 * 2048 * 32];      // inter-layer h pong
__device__ float g_unixw[128 * 256 * 4];
__device__ float g_unih[256 * 128];

// ---------------- fast activations (same as passing R3 version) -----------
__device__ __forceinline__ float fast_ex2(float x) {
    float y; asm("ex2.approx.f32 %0, %1;" : "=f"(y) : "f"(x)); return y;
}
__device__ __forceinline__ float fast_rcp(float x) {
    float y; asm("rcp.approx.f32 %0, %1;" : "=f"(y) : "f"(x)); return y;
}
__device__ __forceinline__ float sigm(float x) {
    float e = fast_ex2(-1.4426950408889634f * x);
    return fast_rcp(1.0f + e);
}
__device__ __forceinline__ float tanh_(float x) {
    float e = fast_ex2(-2.8853900817779268f * x);
    float r = fast_rcp(1.0f + e);
    return fmaf(2.0f, r, -1.0f);
}

// ---------------- packed f32x2 helpers -------------------------------------
__device__ __forceinline__ u64 pack2(float lo, float hi) {
    u64 r; asm("mov.b64 %0, {%1, %2};" : "=l"(r) : "f"(lo), "f"(hi)); return r;
}
__device__ __forceinline__ void unpack2(u64 v, float& lo, float& hi) {
    asm("mov.b64 {%0, %1}, %2;" : "=f"(lo), "=f"(hi) : "l"(v));
}
__device__ __forceinline__ u64 fma2(u64 a, u64 b, u64 c) {
    u64 d; asm("fma.rn.f32x2 %0, %1, %2, %3;" : "=l"(d) : "l"(a), "l"(b), "l"(c)); return d;
}

// ---------------------------------------------------------------------------
// xW GEMM: xw[b][d][t][u*4+q] = bias[d][q*16+u] + sum_k x[b][t][k]*Wih[d][q*16+u][k]
// grid.x = 128 batches * 4 t-chunks (512 t each); block = 128 threads
// thread tid = d*64 + q*16 + u. Weights packed f32x2 in registers.
// SRC: 0 external x param, 1 g_hA, 2 g_hB.
// ---------------------------------------------------------------------------
template <int IN, int SRC>
__global__ void __launch_bounds__(128)
xw_gemm_kernel(const float* __restrict__ xparam,
               const float* __restrict__ Wih,    // [2][64][IN]
               const float* __restrict__ bias)   // [2][64]
{
    const float* __restrict__ xin =
        (SRC == 0) ? xparam : (SRC == 1 ? g_hA : g_hB);

    const int b  = blockIdx.x >> 2;
    const int t0 = (blockIdx.x & 3) * 512;
    const int tid = threadIdx.x;
    const int d = tid >> 6;
    const int q = (tid >> 4) & 3;
    const int u = tid & 15;
    const int g = q * 16 + u;

    u64 w2[IN / 2];
    {
        const float* wr = Wih + (d * 64 + g) * IN;
#pragma unroll
        for (int k = 0; k < IN / 2; k++) w2[k] = pack2(wr[2 * k], wr[2 * k + 1]);
    }
    const float bs = bias[d * 64 + g];

    __shared__ float xs[128 * IN];
    float* __restrict__ gout =
        g_xw + (size_t)((b * 2 + d) * 2048) * 64 + u * 4 + q;

    for (int cc = 0; cc < 4; ++cc) {
        const int tb = t0 + cc * 128;
        __syncthreads();
        const float4* src = (const float4*)(xin + (size_t)(b * 2048 + tb) * IN);
        float4* dst = (float4*)xs;
        for (int i = tid; i < 128 * IN / 4; i += 128) dst[i] = src[i];
        __syncthreads();

#pragma unroll 2
        for (int tt = 0; tt < 128; ++tt) {
            const float4* xr = (const float4*)(xs + tt * IN);
            u64 acc_a = pack2(bs, 0.0f);
            u64 acc_b = pack2(0.0f, 0.0f);
#pragma unroll
            for (int k4 = 0; k4 < IN / 4; k4++) {
                float4 xv = xr[k4];
                acc_a = fma2(pack2(xv.x, xv.y), w2[k4 * 2],     acc_a);
                acc_b = fma2(pack2(xv.z, xv.w), w2[k4 * 2 + 1], acc_b);
            }
            float a0, a1, b0, b1;
            unpack2(acc_a, a0, a1);
            unpack2(acc_b, b0, b1);
            gout[(size_t)(tb + tt) * 64] = (a0 + b0) + (a1 + b1);
        }
    }
}

// ---------------------------------------------------------------------------
// Recurrence: grid = 128 blocks x 32 threads (1 warp each).
// warp w: dir = w>>6, batch pair p = w&63. Lanes 0-15: batch 2p; 16-31: 2p+1.
// Lane u owns all 4 gates of h-element u. xw preacts loaded as float4/lane.
// DST: 1 -> g_hA, 2 -> g_hB.
// ---------------------------------------------------------------------------
template <int DST>
__global__ void __launch_bounds__(32, 1)
rec_kernel(const float* __restrict__ Whh_base)   // [2][64][16] for this layer
{
    const int lane = threadIdx.x;
    const int u    = lane & 15;
    const int half = lane >> 4;
    const int w    = blockIdx.x;
    const int dir  = w >> 6;
    const int b    = (w & 63) * 2 + half;

    const float* __restrict__ Whh = Whh_base + dir * 64 * 16;
    float wi[16], wf[16], wg[16], wo[16];
#pragma unroll
    for (int j = 0; j < 16; j++) {
        wi[j] = Whh[(u)      * 16 + j];
        wf[j] = Whh[(16 + u) * 16 + j];
        wg[j] = Whh[(32 + u) * 16 + j];
        wo[j] = Whh[(48 + u) * 16 + j];
    }

    const int dt     = dir ? -1 : 1;
    const int tstart = dir ? 2047 : 0;

    const float4* __restrict__ xp =
        (const float4*)(g_xw + (size_t)((b * 2 + dir) * 2048) * 64) + u;
    float* __restrict__ outp =
        (DST == 1 ? g_hA : g_hB) + (size_t)b * 2048 * 32 + dir * 16 + u;

    float h = 0.0f, c = 0.0f;

    float4 buf[8];
#pragma unroll
    for (int i = 0; i < 8; i++) buf[i] = xp[(size_t)(tstart + i * dt) * 16];

    int t  = tstart;
    int tl = tstart + 8 * dt;

    for (int s = 0; s < 2048; s += 8) {
        const bool pf = (s + 8 < 2048);
#pragma unroll
        for (int i = 0; i < 8; i++) {
            float4 xw = buf[i];
            if (pf) { buf[i] = xp[(size_t)tl * 16]; tl += dt; }

            float ai0 = xw.x, ai1 = 0.f, af0 = xw.y, af1 = 0.f;
            float ag0 = xw.z, ag1 = 0.f, ao0 = xw.w, ao1 = 0.f;
#pragma unroll
            for (int j = 0; j < 16; j += 2) {
                float h0 = __shfl_sync(FULL, h, j,     16);
                float h1 = __shfl_sync(FULL, h, j + 1, 16);
                ai0 = fmaf(h0, wi[j],     ai0); ai1 = fmaf(h1, wi[j + 1], ai1);
                af0 = fmaf(h0, wf[j],     af0); af1 = fmaf(h1, wf[j + 1], af1);
                ag0 = fmaf(h0, wg[j],     ag0); ag1 = fmaf(h1, wg[j + 1], ag1);
                ao0 = fmaf(h0, wo[j],     ao0); ao1 = fmaf(h1, wo[j + 1], ao1);
            }
            float si = sigm(ai0 + ai1);
            float sf = sigm(af0 + af1);
            float tg = tanh_(ag0 + ag1);
            float so = sigm(ao0 + ao1);

            c = fmaf(sf, c, si * tg);
            h = so * tanh_(c);

            outp[(size_t)t * 32] = h;
            t += dt;
        }
    }
}

// ---------------------------------------------------------------------------
// uni-LSTM layer-0 input projection on downsampled biLSTM output (g_hB).
// ---------------------------------------------------------------------------
__global__ void uni_xw_kernel(const float* __restrict__ uWih0,  // [4][32]
                              const float* __restrict__ ub)     // [4][4]
{
    int idx = blockIdx.x * blockDim.x + threadIdx.x;  // 0..32767
    if (idx >= 128 * 256) return;
    int b  = idx >> 8;
    int tt = idx & 255;
    const float* __restrict__ xr = g_hB + (size_t)(b * 2048 + (tt * 8 + 7)) * 32;
    float x[32];
#pragma unroll
    for (int k = 0; k < 32; k++) x[k] = xr[k];
#pragma unroll
    for (int g = 0; g < 4; g++) {
        float acc = __ldg(&ub[g]);
#pragma unroll
        for (int k = 0; k < 32; k++) acc = fmaf(x[k], __ldg(&uWih0[g * 32 + k]), acc);
        g_unixw[idx * 4 + g] = acc;
    }
}

// ---------------------------------------------------------------------------
// 4-layer unidirectional LSTM, H=1. One thread per batch.
// ---------------------------------------------------------------------------
__global__ void uni_rec_kernel(const float* __restrict__ uWih,  // [3][4][1]
                               const float* __restrict__ uWhh,  // [4][4][1]
                               const float* __restrict__ ub,    // [4][4]
                               float* __restrict__ outp)        // [128][256]
{
    int b = blockIdx.x * blockDim.x + threadIdx.x;
    if (b >= 128) return;

    {
        float h = 0.f, c = 0.f;
        const float w0 = uWhh[0], w1 = uWhh[1], w2 = uWhh[2], w3 = uWhh[3];
        for (int t = 0; t < 256; t++) {
            const float* xw = &g_unixw[(b * 256 + t) * 4];
            float gi = fmaf(h, w0, xw[0]);
            float gf = fmaf(h, w1, xw[1]);
            float gg = fmaf(h, w2, xw[2]);
            float go = fmaf(h, w3, xw[3]);
            c = fmaf(sigm(gf), c, sigm(gi) * tanh_(gg));
            h = sigm(go) * tanh_(c);
            g_unih[t * 128 + b] = h;
        }
    }
    for (int l = 1; l < 4; l++) {
        const float* wih = uWih + (l - 1) * 4;
        const float* whh = uWhh + l * 4;
        const float* bb  = ub + l * 4;
        const float vi0 = wih[0], vi1 = wih[1], vi2 = wih[2], vi3 = wih[3];
        const float w0 = whh[0], w1 = whh[1], w2 = whh[2], w3 = whh[3];
        const float c0 = bb[0], c1 = bb[1], c2 = bb[2], c3 = bb[3];
        float h = 0.f, c = 0.f;
        for (int t = 0; t < 256; t++) {
            float xx = g_unih[t * 128 + b];
            float gi = fmaf(h, w0, fmaf(xx, vi0, c0));
            float gf = fmaf(h, w1, fmaf(xx, vi1, c1));
            float gg = fmaf(h, w2, fmaf(xx, vi2, c2));
            float go = fmaf(h, w3, fmaf(xx, vi3, c3));
            c = fmaf(sigm(gf), c, sigm(gi) * tanh_(gg));
            h = sigm(go) * tanh_(c);
            if (l == 3) outp[b * 256 + t] = h;
            else        g_unih[t * 128 + b] = h;
        }
    }
}

// ---------------------------------------------------------------------------
extern "C" void kernel_launch(void* const* d_in, const int* in_sizes, int n_in,
                              void* d_out, int out_size)
{
    const float* x     = (const float*)d_in[0];  // (128,2048,24)
    const float* bWih0 = (const float*)d_in[1];  // (2,64,24)
    const float* bWih  = (const float*)d_in[2];  // (3,2,64,32)
    const float* bWhh  = (const float*)d_in[3];  // (4,2,64,16)
    const float* bb    = (const float*)d_in[4];  // (4,2,64)
    const float* uWih0 = (const float*)d_in[5];  // (4,32)
    const float* uWih  = (const float*)d_in[6];  // (3,4,1)
    const float* uWhh  = (const float*)d_in[7];  // (4,4,1)
    const float* ub    = (const float*)d_in[8];  // (4,4)
    float* out = (float*)d_out;                  // (128,256,1)

    dim3 ggrid(512), gblock(128);
    dim3 rgrid(128), rblock(32);

    // layer 0
    xw_gemm_kernel<24, 0><<<ggrid, gblock>>>(x, bWih0, bb + 0 * 128);
    rec_kernel<1><<<rgrid, rblock>>>(bWhh + 0 * 2 * 64 * 16);           // -> g_hA
    // layer 1
    xw_gemm_kernel<32, 1><<<ggrid, gblock>>>(nullptr, bWih + 0 * 2 * 64 * 32, bb + 1 * 128);
    rec_kernel<2><<<rgrid, rblock>>>(bWhh + 1 * 2 * 64 * 16);           // -> g_hB
    // layer 2
    xw_gemm_kernel<32, 2><<<ggrid, gblock>>>(nullptr, bWih + 1 * 2 * 64 * 32, bb + 2 * 128);
    rec_kernel<1><<<rgrid, rblock>>>(bWhh + 2 * 2 * 64 * 16);           // -> g_hA
    // layer 3
    xw_gemm_kernel<32, 1><<<ggrid, gblock>>>(nullptr, bWih + 2 * 2 * 64 * 32, bb + 3 * 128);
    rec_kernel<2><<<rgrid, rblock>>>(bWhh + 3 * 2 * 64 * 16);           // -> g_hB

    // uni-LSTM stack
    uni_xw_kernel<<<128, 256>>>(uWih0, ub);
    uni_rec_kernel<<<4, 32>>>(uWih, uWhh, ub, out);
}

// round 9
// speedup vs baseline: 1.7757x; 1.3847x over previous
#include <cuda_runtime.h>

#define FULL 0xffffffffu
typedef unsigned long long u64;

// ---------------------------------------------------------------------------
// pitch_predictor: 4-layer biLSTM (B=128,T=2048,H=16) -> x[:,7::8,:] ->
//                  4-layer uniLSTM (H=1) -> out (128,256,1) fp32
// Phase split per layer: parallel xW GEMM (throughput) + recurrence warps
// (latency). Recurrence: 1 warp per (batch,dir), 2 gates/lane, dual-redundant
// cell state, tanh.approx activations, float2 preact stream with prefetch.
// ---------------------------------------------------------------------------

__device__ float g_xw[128 * 2 * 2048 * 64];  // gate preacts (bias folded); packed layout below
__device__ float g_hA[128 * 2048 * 32];      // inter-layer h ping
__device__ float g_hB[128 * 2048 * 32];      // inter-layer h pong
__device__ float g_unixw[128 * 256 * 4];
__device__ float g_unih[256 * 128];

// ---------------- activations ----------------------------------------------
__device__ __forceinline__ float fast_ex2(float x) {
    float y; asm("ex2.approx.f32 %0, %1;" : "=f"(y) : "f"(x)); return y;
}
__device__ __forceinline__ float fast_rcp(float x) {
    float y; asm("rcp.approx.f32 %0, %1;" : "=f"(y) : "f"(x)); return y;
}
// exact-ish versions (uni stack)
__device__ __forceinline__ float sigm(float x) {
    float e = fast_ex2(-1.4426950408889634f * x);
    return fast_rcp(1.0f + e);
}
__device__ __forceinline__ float tanh_(float x) {
    float e = fast_ex2(-2.8853900817779268f * x);
    float r = fast_rcp(1.0f + e);
    return fmaf(2.0f, r, -1.0f);
}
// single-MUFU tanh (hot recurrence)
__device__ __forceinline__ float tanh_fast(float x) {
    float y; asm("tanh.approx.f32 %0, %1;" : "=f"(y) : "f"(x)); return y;
}
__device__ __forceinline__ float sigm_fast(float x) {
    return fmaf(0.5f, tanh_fast(0.5f * x), 0.5f);
}

// ---------------- packed f32x2 helpers (GEMM) -------------------------------
__device__ __forceinline__ u64 pack2(float lo, float hi) {
    u64 r; asm("mov.b64 %0, {%1, %2};" : "=l"(r) : "f"(lo), "f"(hi)); return r;
}
__device__ __forceinline__ void unpack2(u64 v, float& lo, float& hi) {
    asm("mov.b64 {%0, %1}, %2;" : "=f"(lo), "=f"(hi) : "l"(v));
}
__device__ __forceinline__ u64 fma2(u64 a, u64 b, u64 c) {
    u64 d; asm("fma.rn.f32x2 %0, %1, %2, %3;" : "=l"(d) : "l"(a), "l"(b), "l"(c)); return d;
}

// ---------------------------------------------------------------------------
// xW GEMM. Row layout per (b,dir,t): 64 floats, packed for the rec kernel:
//   slot 2u   = i_u preact,  slot 2u+1  = g_u preact      (lanes 0..15)
//   slot 32+2u= f_u preact,  slot 33+2u = o_u preact      (lanes 16..31)
// thread tid = d*64 + q*16 + u (q = gate block i/f/g/o), slot = ((q&1)<<5) + 2u + (q>>1)
// grid.x = 128 batches * 4 t-chunks; SRC: 0 external, 1 g_hA, 2 g_hB.
// ---------------------------------------------------------------------------
template <int IN, int SRC>
__global__ void __launch_bounds__(128)
xw_gemm_kernel(const float* __restrict__ xparam,
               const float* __restrict__ Wih,    // [2][64][IN]
               const float* __restrict__ bias)   // [2][64]
{
    const float* __restrict__ xin =
        (SRC == 0) ? xparam : (SRC == 1 ? g_hA : g_hB);

    const int b  = blockIdx.x >> 2;
    const int t0 = (blockIdx.x & 3) * 512;
    const int tid = threadIdx.x;
    const int d = tid >> 6;
    const int q = (tid >> 4) & 3;
    const int u = tid & 15;
    const int g = q * 16 + u;
    const int slot = ((q & 1) << 5) + 2 * u + (q >> 1);

    u64 w2[IN / 2];
    {
        const float* wr = Wih + (d * 64 + g) * IN;
#pragma unroll
        for (int k = 0; k < IN / 2; k++) w2[k] = pack2(wr[2 * k], wr[2 * k + 1]);
    }
    const float bs = bias[d * 64 + g];

    __shared__ float xs[128 * IN];
    float* __restrict__ gout =
        g_xw + (size_t)((b * 2 + d) * 2048) * 64 + slot;

    for (int cc = 0; cc < 4; ++cc) {
        const int tb = t0 + cc * 128;
        __syncthreads();
        const float4* src = (const float4*)(xin + (size_t)(b * 2048 + tb) * IN);
        float4* dst = (float4*)xs;
        for (int i = tid; i < 128 * IN / 4; i += 128) dst[i] = src[i];
        __syncthreads();

#pragma unroll 2
        for (int tt = 0; tt < 128; ++tt) {
            const float4* xr = (const float4*)(xs + tt * IN);
            u64 acc_a = pack2(bs, 0.0f);
            u64 acc_b = pack2(0.0f, 0.0f);
#pragma unroll
            for (int k4 = 0; k4 < IN / 4; k4++) {
                float4 xv = xr[k4];
                acc_a = fma2(pack2(xv.x, xv.y), w2[k4 * 2],     acc_a);
                acc_b = fma2(pack2(xv.z, xv.w), w2[k4 * 2 + 1], acc_b);
            }
            float a0, a1, b0, b1;
            unpack2(acc_a, a0, a1);
            unpack2(acc_b, b0, b1);
            gout[(size_t)(tb + tt) * 64] = (a0 + b0) + (a1 + b1);
        }
    }
}

// ---------------------------------------------------------------------------
// Recurrence: 64 blocks x 128 threads; warp wp handles combo = blk*4+wp:
// b = combo & 127, dir = combo >> 7. One full warp per recurrence.
// Lane u<16: gates {i_u, g_u}; lane u+16: gates {f_u, o_u}.
// Lanes u and u+16 both maintain c[u], h[u] (identical) -> one xor16 exchange.
// DST: 1 -> g_hA, 2 -> g_hB.
// ---------------------------------------------------------------------------
template <int DST>
__global__ void __launch_bounds__(128, 1)
rec_kernel(const float* __restrict__ Whh_base)   // [2][64][16] for this layer
{
    const int lane  = threadIdx.x & 31;
    const int u     = lane & 15;
    const bool hi   = (lane >= 16);
    const int combo = blockIdx.x * 4 + (threadIdx.x >> 5);
    const int b     = combo & 127;
    const int dir   = combo >> 7;

    const float* __restrict__ Whh = Whh_base + dir * 64 * 16;
    const int gA = hi ? (16 + u) : u;        // f_u : i_u
    const int gB = hi ? (48 + u) : (32 + u); // o_u : g_u

    float whA[16], whB[16];
#pragma unroll
    for (int j = 0; j < 16; j++) {
        whA[j] = Whh[gA * 16 + j];
        whB[j] = Whh[gB * 16 + j];
    }

    const int dt     = dir ? -1 : 1;
    const int tstart = dir ? 2047 : 0;

    const float2* __restrict__ xp =
        (const float2*)(g_xw + (size_t)((b * 2 + dir) * 2048) * 64) + lane;
    float* __restrict__ outp =
        (DST == 1 ? g_hA : g_hB) + (size_t)b * 2048 * 32 + dir * 16 + u;

    float h = 0.0f, c = 0.0f;

    float2 buf[8];
#pragma unroll
    for (int i = 0; i < 8; i++) buf[i] = __ldg(&xp[(size_t)(tstart + i * dt) * 32]);

    int t  = tstart;
    int tl = tstart + 8 * dt;

    for (int s = 0; s < 2048; s += 8) {
        const bool pf = (s + 8 < 2048);
#pragma unroll
        for (int i = 0; i < 8; i++) {
            float2 xw = buf[i];
            if (pf) { buf[i] = __ldg(&xp[(size_t)tl * 32]); tl += dt; }

            // recurrent dots (h broadcast from lanes 0..15; duplicated on 16..31)
            float a0 = xw.x, a1 = 0.f, b0 = xw.y, b1 = 0.f;
#pragma unroll
            for (int j = 0; j < 16; j += 2) {
                float h0 = __shfl_sync(FULL, h, j);
                float h1 = __shfl_sync(FULL, h, j + 1);
                a0 = fmaf(h0, whA[j],     a0);
                a1 = fmaf(h1, whA[j + 1], a1);
                b0 = fmaf(h0, whB[j],     b0);
                b1 = fmaf(h1, whB[j + 1], b1);
            }
            float preA = a0 + a1;   // i (lo) | f (hi)
            float preB = b0 + b1;   // g (lo) | o (hi)

            // activations: sA = sigm(preA); vB = lo ? tanh(preB) : sigm(preB)
            float sA = sigm_fast(preA);
            float m  = hi ? 0.5f * preB : preB;
            float r  = tanh_fast(m);
            float vB = hi ? fmaf(0.5f, r, 0.5f) : r;

            float myA = hi ? sA : sA * vB;   // sig(f) | sig(i)*tanh(g)
            float oA  = __shfl_xor_sync(FULL, myA, 16);
            float oB  = __shfl_xor_sync(FULL, vB,  16);

            float prod = hi ? oA  : myA;     // sig(i)*tanh(g)
            float sf   = hi ? myA : oA;      // sig(f)
            float so   = hi ? vB  : oB;      // sig(o)

            c = fmaf(sf, c, prod);
            h = so * tanh_fast(c);

            if (!hi) outp[(size_t)t * 32] = h;
            t += dt;
        }
    }
}

// ---------------------------------------------------------------------------
// uni-LSTM layer-0 input projection on downsampled biLSTM output (g_hB).
// ---------------------------------------------------------------------------
__global__ void uni_xw_kernel(const float* __restrict__ uWih0,  // [4][32]
                              const float* __restrict__ ub)     // [4][4]
{
    int idx = blockIdx.x * blockDim.x + threadIdx.x;  // 0..32767
    if (idx >= 128 * 256) return;
    int b  = idx >> 8;
    int tt = idx & 255;
    const float* __restrict__ xr = g_hB + (size_t)(b * 2048 + (tt * 8 + 7)) * 32;
    float x[32];
#pragma unroll
    for (int k = 0; k < 32; k++) x[k] = xr[k];
#pragma unroll
    for (int g = 0; g < 4; g++) {
        float acc = __ldg(&ub[g]);
#pragma unroll
        for (int k = 0; k < 32; k++) acc = fmaf(x[k], __ldg(&uWih0[g * 32 + k]), acc);
        g_unixw[idx * 4 + g] = acc;
    }
}

// ---------------------------------------------------------------------------
// 4-layer unidirectional LSTM, H=1. One thread per batch. Exact activations.
// ---------------------------------------------------------------------------
__global__ void uni_rec_kernel(const float* __restrict__ uWih,  // [3][4][1]
                               const float* __restrict__ uWhh,  // [4][4][1]
                               const float* __restrict__ ub,    // [4][4]
                               float* __restrict__ outp)        // [128][256]
{
    int b = blockIdx.x * blockDim.x + threadIdx.x;
    if (b >= 128) return;

    {
        float h = 0.f, c = 0.f;
        const float w0 = uWhh[0], w1 = uWhh[1], w2 = uWhh[2], w3 = uWhh[3];
        for (int t = 0; t < 256; t++) {
            const float* xw = &g_unixw[(b * 256 + t) * 4];
            float gi = fmaf(h, w0, xw[0]);
            float gf = fmaf(h, w1, xw[1]);
            float gg = fmaf(h, w2, xw[2]);
            float go = fmaf(h, w3, xw[3]);
            c = fmaf(sigm(gf), c, sigm(gi) * tanh_(gg));
            h = sigm(go) * tanh_(c);
            g_unih[t * 128 + b] = h;
        }
    }
    for (int l = 1; l < 4; l++) {
        const float* wih = uWih + (l - 1) * 4;
        const float* whh = uWhh + l * 4;
        const float* bb  = ub + l * 4;
        const float vi0 = wih[0], vi1 = wih[1], vi2 = wih[2], vi3 = wih[3];
        const float w0 = whh[0], w1 = whh[1], w2 = whh[2], w3 = whh[3];
        const float c0 = bb[0], c1 = bb[1], c2 = bb[2], c3 = bb[3];
        float h = 0.f, c = 0.f;
        for (int t = 0; t < 256; t++) {
            float xx = g_unih[t * 128 + b];
            float gi = fmaf(h, w0, fmaf(xx, vi0, c0));
            float gf = fmaf(h, w1, fmaf(xx, vi1, c1));
            float gg = fmaf(h, w2, fmaf(xx, vi2, c2));
            float go = fmaf(h, w3, fmaf(xx, vi3, c3));
            c = fmaf(sigm(gf), c, sigm(gi) * tanh_(gg));
            h = sigm(go) * tanh_(c);
            if (l == 3) outp[b * 256 + t] = h;
            else        g_unih[t * 128 + b] = h;
        }
    }
}

// ---------------------------------------------------------------------------
extern "C" void kernel_launch(void* const* d_in, const int* in_sizes, int n_in,
                              void* d_out, int out_size)
{
    const float* x     = (const float*)d_in[0];  // (128,2048,24)
    const float* bWih0 = (const float*)d_in[1];  // (2,64,24)
    const float* bWih  = (const float*)d_in[2];  // (3,2,64,32)
    const float* bWhh  = (const float*)d_in[3];  // (4,2,64,16)
    const float* bb    = (const float*)d_in[4];  // (4,2,64)
    const float* uWih0 = (const float*)d_in[5];  // (4,32)
    const float* uWih  = (const float*)d_in[6];  // (3,4,1)
    const float* uWhh  = (const float*)d_in[7];  // (4,4,1)
    const float* ub    = (const float*)d_in[8];  // (4,4)
    float* out = (float*)d_out;                  // (128,256,1)

    dim3 ggrid(512), gblock(128);
    dim3 rgrid(64), rblock(128);

    // layer 0
    xw_gemm_kernel<24, 0><<<ggrid, gblock>>>(x, bWih0, bb + 0 * 128);
    rec_kernel<1><<<rgrid, rblock>>>(bWhh + 0 * 2 * 64 * 16);           // -> g_hA
    // layer 1
    xw_gemm_kernel<32, 1><<<ggrid, gblock>>>(nullptr, bWih + 0 * 2 * 64 * 32, bb + 1 * 128);
    rec_kernel<2><<<rgrid, rblock>>>(bWhh + 1 * 2 * 64 * 16);           // -> g_hB
    // layer 2
    xw_gemm_kernel<32, 2><<<ggrid, gblock>>>(nullptr, bWih + 1 * 2 * 64 * 32, bb + 2 * 128);
    rec_kernel<1><<<rgrid, rblock>>>(bWhh + 2 * 2 * 64 * 16);           // -> g_hA
    // layer 3
    xw_gemm_kernel<32, 1><<<ggrid, gblock>>>(nullptr, bWih + 2 * 2 * 64 * 32, bb + 3 * 128);
    rec_kernel<2><<<rgrid, rblock>>>(bWhh + 3 * 2 * 64 * 16);           // -> g_hB

    // uni-LSTM stack
    uni_xw_kernel<<<128, 256>>>(uWih0, ub);
    uni_rec_kernel<<<4, 32>>>(uWih, uWhh, ub, out);
}

// round 11
// speedup vs baseline: 1.9391x; 1.0920x over previous
#include <cuda_runtime.h>

#define FULL 0xffffffffu
typedef unsigned long long u64;

// ---------------------------------------------------------------------------
// pitch_predictor: 4-layer biLSTM (B=128,T=2048,H=16) -> x[:,7::8,:] ->
//                  4-layer uniLSTM (H=1) -> out (128,256,1) fp32
// Per layer: parallel xW GEMM (throughput) + recurrence warps (latency).
// Recurrence v3: 16 lanes per recurrence (2 per warp), lane owns all 4 gates
// of one h element, packed f32x2 gate dots, tanh.approx activations,
// no inter-lane gate exchange on the critical chain.
// ---------------------------------------------------------------------------

__device__ float g_xw[128 * 2 * 2048 * 64];  // preacts (bias folded): slot = u*4 + gate
__device__ float g_hA[128 * 2048 * 32];      // inter-layer h ping
__device__ float g_hB[128 * 2048 * 32];      // inter-layer h pong
__device__ float g_unixw[128 * 256 * 4];
__device__ float g_unih[256 * 128];

// ---------------- activations ----------------------------------------------
__device__ __forceinline__ float tanh_fast(float x) {
    float y; asm("tanh.approx.f32 %0, %1;" : "=f"(y) : "f"(x)); return y;
}
__device__ __forceinline__ float sigm_fast(float x) {
    return fmaf(0.5f, tanh_fast(0.5f * x), 0.5f);
}

// ---------------- packed f32x2 helpers --------------------------------------
__device__ __forceinline__ u64 pack2(float lo, float hi) {
    u64 r; asm("mov.b64 %0, {%1, %2};" : "=l"(r) : "f"(lo), "f"(hi)); return r;
}
__device__ __forceinline__ void unpack2(u64 v, float& lo, float& hi) {
    asm("mov.b64 {%0, %1}, %2;" : "=f"(lo), "=f"(hi) : "l"(v));
}
__device__ __forceinline__ u64 fma2(u64 a, u64 b, u64 c) {
    u64 d; asm("fma.rn.f32x2 %0, %1, %2, %3;" : "=l"(d) : "l"(a), "l"(b), "l"(c)); return d;
}
__device__ __forceinline__ u64 add2(u64 a, u64 b) {
    u64 d; asm("add.rn.f32x2 %0, %1, %2;" : "=l"(d) : "l"(a), "l"(b)); return d;
}

// ---------------------------------------------------------------------------
// xW GEMM. Output row per (b,dir,t): 64 floats, slot = u*4 + q
// (q = 0:i 1:f 2:g 3:o), so lane u's 4 preacts are one contiguous float4.
// thread tid = d*64 + q*16 + u. grid.x = 128 batches * 8 t-chunks (256 t).
// SRC: 0 external x, 1 g_hA, 2 g_hB.
// ---------------------------------------------------------------------------
template <int IN, int SRC>
__global__ void __launch_bounds__(128)
xw_gemm_kernel(const float* __restrict__ xparam,
               const float* __restrict__ Wih,    // [2][64][IN]
               const float* __restrict__ bias)   // [2][64]
{
    const float* __restrict__ xin =
        (SRC == 0) ? xparam : (SRC == 1 ? g_hA : g_hB);

    const int b  = blockIdx.x >> 3;
    const int t0 = (blockIdx.x & 7) * 256;
    const int tid = threadIdx.x;
    const int d = tid >> 6;
    const int q = (tid >> 4) & 3;
    const int u = tid & 15;
    const int g = q * 16 + u;
    const int slot = u * 4 + q;

    u64 w2[IN / 2];
    {
        const float* wr = Wih + (d * 64 + g) * IN;
#pragma unroll
        for (int k = 0; k < IN / 2; k++) w2[k] = pack2(wr[2 * k], wr[2 * k + 1]);
    }
    const float bs = bias[d * 64 + g];

    __shared__ float xs[128 * IN];
    float* __restrict__ gout =
        g_xw + (size_t)((b * 2 + d) * 2048) * 64 + slot;

    for (int cc = 0; cc < 2; ++cc) {
        const int tb = t0 + cc * 128;
        __syncthreads();
        const float4* src = (const float4*)(xin + (size_t)(b * 2048 + tb) * IN);
        float4* dst = (float4*)xs;
        for (int i = tid; i < 128 * IN / 4; i += 128) dst[i] = src[i];
        __syncthreads();

#pragma unroll 2
        for (int tt = 0; tt < 128; ++tt) {
            const float4* xr = (const float4*)(xs + tt * IN);
            u64 acc_a = pack2(bs, 0.0f);
            u64 acc_b = pack2(0.0f, 0.0f);
#pragma unroll
            for (int k4 = 0; k4 < IN / 4; k4++) {
                float4 xv = xr[k4];
                acc_a = fma2(pack2(xv.x, xv.y), w2[k4 * 2],     acc_a);
                acc_b = fma2(pack2(xv.z, xv.w), w2[k4 * 2 + 1], acc_b);
            }
            float a0, a1, b0, b1;
            unpack2(acc_a, a0, a1);
            unpack2(acc_b, b0, b1);
            gout[(size_t)(tb + tt) * 64] = (a0 + b0) + (a1 + b1);
        }
    }
}

// ---------------------------------------------------------------------------
// Recurrence v3: 32 blocks x 128 threads; global warp w = blk*4 + wp (128
// warps). dir = w>>6; lanes 0-15 -> batch (w&63)*2, lanes 16-31 -> +1.
// Lane u owns i/f/g/o of h-element u; packed (i,f) & (g,o) f32x2 dots;
// width-16 shfl broadcasts h to both halves at once. DST: 1 g_hA, 2 g_hB.
// ---------------------------------------------------------------------------
template <int DST>
__global__ void __launch_bounds__(128, 1)
rec_kernel(const float* __restrict__ Whh_base)   // [2][64][16] for this layer
{
    const int lane = threadIdx.x & 31;
    const int u    = lane & 15;
    const int half = lane >> 4;
    const int w    = blockIdx.x * 4 + (threadIdx.x >> 5);
    const int dir  = w >> 6;
    const int b    = (w & 63) * 2 + half;

    const float* __restrict__ Whh = Whh_base + dir * 64 * 16;

    u64 wif2[16], wgo2[16];
#pragma unroll
    for (int j = 0; j < 16; j++) {
        wif2[j] = pack2(Whh[(u)      * 16 + j], Whh[(16 + u) * 16 + j]);
        wgo2[j] = pack2(Whh[(32 + u) * 16 + j], Whh[(48 + u) * 16 + j]);
    }

    const int dt     = dir ? -1 : 1;
    const int tstart = dir ? 2047 : 0;

    const float4* __restrict__ xp =
        (const float4*)(g_xw + (size_t)((b * 2 + dir) * 2048) * 64) + u;
    float* __restrict__ outp =
        (DST == 1 ? g_hA : g_hB) + (size_t)b * 2048 * 32 + dir * 16 + u;

    float h = 0.0f, c = 0.0f;

    float4 buf[8];
#pragma unroll
    for (int i = 0; i < 8; i++) buf[i] = __ldg(&xp[(size_t)(tstart + i * dt) * 16]);

    int t  = tstart;
    int tl = tstart + 8 * dt;

    for (int s = 0; s < 2048; s += 8) {
        const bool pf = (s + 8 < 2048);
#pragma unroll
        for (int i = 0; i < 8; i++) {
            float4 xw = buf[i];
            if (pf) { buf[i] = __ldg(&xp[(size_t)tl * 16]); tl += dt; }

            // packed recurrent dots: (i,f) and (g,o), 2-way split chains
            u64 aif0 = pack2(xw.x, xw.y), aif1 = pack2(0.f, 0.f);
            u64 ago0 = pack2(xw.z, xw.w), ago1 = pack2(0.f, 0.f);
#pragma unroll
            for (int j = 0; j < 16; j += 2) {
                float h0 = __shfl_sync(FULL, h, j,     16);
                float h1 = __shfl_sync(FULL, h, j + 1, 16);
                u64 hp0 = pack2(h0, h0);
                u64 hp1 = pack2(h1, h1);
                aif0 = fma2(hp0, wif2[j],     aif0);
                aif1 = fma2(hp1, wif2[j + 1], aif1);
                ago0 = fma2(hp0, wgo2[j],     ago0);
                ago1 = fma2(hp1, wgo2[j + 1], ago1);
            }
            float ai, af, ag, ao;
            unpack2(add2(aif0, aif1), ai, af);
            unpack2(add2(ago0, ago1), ag, ao);

            // MUFU order: g first (longest downstream), then i, f, o
            float tg = tanh_fast(ag);
            float si = sigm_fast(ai);
            float sf = sigm_fast(af);
            float so = sigm_fast(ao);

            c = fmaf(sf, c, si * tg);
            h = so * tanh_fast(c);

            outp[(size_t)t * 32] = h;
            t += dt;
        }
    }
}

// ---------------------------------------------------------------------------
// uni-LSTM layer-0 input projection on downsampled biLSTM output (g_hB).
// ---------------------------------------------------------------------------
__global__ void uni_xw_kernel(const float* __restrict__ uWih0,  // [4][32]
                              const float* __restrict__ ub)     // [4][4]
{
    int idx = blockIdx.x * blockDim.x + threadIdx.x;  // 0..32767
    if (idx >= 128 * 256) return;
    int b  = idx >> 8;
    int tt = idx & 255;
    const float* __restrict__ xr = g_hB + (size_t)(b * 2048 + (tt * 8 + 7)) * 32;
    float x[32];
#pragma unroll
    for (int k = 0; k < 32; k++) x[k] = xr[k];
#pragma unroll
    for (int g = 0; g < 4; g++) {
        float acc = __ldg(&ub[g]);
#pragma unroll
        for (int k = 0; k < 32; k++) acc = fmaf(x[k], __ldg(&uWih0[g * 32 + k]), acc);
        g_unixw[idx * 4 + g] = acc;
    }
}

// ---------------------------------------------------------------------------
// 4-layer unidirectional LSTM, H=1. One thread per batch.
// ---------------------------------------------------------------------------
__global__ void uni_rec_kernel(const float* __restrict__ uWih,  // [3][4][1]
                               const float* __restrict__ uWhh,  // [4][4][1]
                               const float* __restrict__ ub,    // [4][4]
                               float* __restrict__ outp)        // [128][256]
{
    int b = blockIdx.x * blockDim.x + threadIdx.x;
    if (b >= 128) return;

    {
        float h = 0.f, c = 0.f;
        const float w0 = uWhh[0], w1 = uWhh[1], w2 = uWhh[2], w3 = uWhh[3];
        const float4* xwp = (const float4*)(g_unixw) + b * 256;
        for (int t = 0; t < 256; t++) {
            float4 xw = xwp[t];
            float gi = fmaf(h, w0, xw.x);
            float gf = fmaf(h, w1, xw.y);
            float gg = fmaf(h, w2, xw.z);
            float go = fmaf(h, w3, xw.w);
            c = fmaf(sigm_fast(gf), c, sigm_fast(gi) * tanh_fast(gg));
            h = sigm_fast(go) * tanh_fast(c);
            g_unih[t * 128 + b] = h;
        }
    }
    for (int l = 1; l < 4; l++) {
        const float* wih = uWih + (l - 1) * 4;
        const float* whh = uWhh + l * 4;
        const float* bb  = ub + l * 4;
        const float vi0 = wih[0], vi1 = wih[1], vi2 = wih[2], vi3 = wih[3];
        const float w0 = whh[0], w1 = whh[1], w2 = whh[2], w3 = whh[3];
        const float c0 = bb[0], c1 = bb[1], c2 = bb[2], c3 = bb[3];
        float h = 0.f, c = 0.f;
        for (int t = 0; t < 256; t++) {
            float xx = g_unih[t * 128 + b];
            float gi = fmaf(h, w0, fmaf(xx, vi0, c0));
            float gf = fmaf(h, w1, fmaf(xx, vi1, c1));
            float gg = fmaf(h, w2, fmaf(xx, vi2, c2));
            float go = fmaf(h, w3, fmaf(xx, vi3, c3));
            c = fmaf(sigm_fast(gf), c, sigm_fast(gi) * tanh_fast(gg));
            h = sigm_fast(go) * tanh_fast(c);
            if (l == 3) outp[b * 256 + t] = h;
            else        g_unih[t * 128 + b] = h;
        }
    }
}

// ---------------------------------------------------------------------------
extern "C" void kernel_launch(void* const* d_in, const int* in_sizes, int n_in,
                              void* d_out, int out_size)
{
    const float* x     = (const float*)d_in[0];  // (128,2048,24)
    const float* bWih0 = (const float*)d_in[1];  // (2,64,24)
    const float* bWih  = (const float*)d_in[2];  // (3,2,64,32)
    const float* bWhh  = (const float*)d_in[3];  // (4,2,64,16)
    const float* bb    = (const float*)d_in[4];  // (4,2,64)
    const float* uWih0 = (const float*)d_in[5];  // (4,32)
    const float* uWih  = (const float*)d_in[6];  // (3,4,1)
    const float* uWhh  = (const float*)d_in[7];  // (4,4,1)
    const float* ub    = (const float*)d_in[8];  // (4,4)
    float* out = (float*)d_out;                  // (128,256,1)

    dim3 ggrid(1024), gblock(128);
    dim3 rgrid(32), rblock(128);

    // layer 0
    xw_gemm_kernel<24, 0><<<ggrid, gblock>>>(x, bWih0, bb + 0 * 128);
    rec_kernel<1><<<rgrid, rblock>>>(bWhh + 0 * 2 * 64 * 16);           // -> g_hA
    // layer 1
    xw_gemm_kernel<32, 1><<<ggrid, gblock>>>(nullptr, bWih + 0 * 2 * 64 * 32, bb + 1 * 128);
    rec_kernel<2><<<rgrid, rblock>>>(bWhh + 1 * 2 * 64 * 16);           // -> g_hB
    // layer 2
    xw_gemm_kernel<32, 2><<<ggrid, gblock>>>(nullptr, bWih + 1 * 2 * 64 * 32, bb + 2 * 128);
    rec_kernel<1><<<rgrid, rblock>>>(bWhh + 2 * 2 * 64 * 16);           // -> g_hA
    // layer 3
    xw_gemm_kernel<32, 1><<<ggrid, gblock>>>(nullptr, bWih + 2 * 2 * 64 * 32, bb + 3 * 128);
    rec_kernel<2><<<rgrid, rblock>>>(bWhh + 3 * 2 * 64 * 16);           // -> g_hB

    // uni-LSTM stack
    uni_xw_kernel<<<128, 256>>>(uWih0, ub);
    uni_rec_kernel<<<4, 32>>>(uWih, uWhh, ub, out);
}